// round 1
// baseline (speedup 1.0000x reference)
#include <cuda_runtime.h>

#define DD 24
#define HH 48
#define WW 64
#define NV (DD*HH*WW)        /* 73728  interior voxels */
#define DP (DD+2)
#define HP (HH+2)
#define WP (WW+2)
#define NP (DP*HP*WP)        /* 85800  padded voxels */
#define CIN 32
#define COUT 48

#define TD 2
#define TH 8
#define TILE_ELEMS ((TD+2)*(TH+2)*WP)   /* 4*10*66 = 2640 */

// scratch (allocation-free rule: __device__ globals)
__device__ float g_q[COUT * NV];   // ~14.2 MB
__device__ float g_k[COUT * NP];   // ~16.5 MB
__device__ float g_v[COUT * NP];   // ~16.5 MB

// ---------------------------------------------------------------------------
// Pass 1: 1x1x1 conv channel-GEMMs.  blockIdx.y selects q(0)/k(1)/v(2).
// q written on interior grid; k/v written on the zero-padded grid.
// One thread = one voxel, holds the 32-deep x column in registers, produces
// all 48 output channels with weights broadcast from smem.
// ---------------------------------------------------------------------------
__global__ void qkv_kernel(const float* __restrict__ x,
                           const float* __restrict__ Wq,
                           const float* __restrict__ Wk,
                           const float* __restrict__ Wv) {
    __shared__ float sw[COUT * CIN];
    const int which = blockIdx.y;
    const float* Wsel = (which == 0) ? Wq : ((which == 1) ? Wk : Wv);
    for (int i = threadIdx.x; i < COUT * CIN; i += blockDim.x) sw[i] = Wsel[i];
    __syncthreads();

    const int v = blockIdx.x * blockDim.x + threadIdx.x;

    if (which == 0) {
        if (v >= NV) return;
        float xs[CIN];
        #pragma unroll
        for (int c = 0; c < CIN; c++) xs[c] = x[c * NV + v];
        #pragma unroll
        for (int o = 0; o < COUT; o++) {
            float a0 = 0.f, a1 = 0.f, a2 = 0.f, a3 = 0.f;
            #pragma unroll
            for (int c = 0; c < CIN; c += 4) {
                a0 = fmaf(sw[o * CIN + c + 0], xs[c + 0], a0);
                a1 = fmaf(sw[o * CIN + c + 1], xs[c + 1], a1);
                a2 = fmaf(sw[o * CIN + c + 2], xs[c + 2], a2);
                a3 = fmaf(sw[o * CIN + c + 3], xs[c + 3], a3);
            }
            g_q[o * NV + v] = (a0 + a1) + (a2 + a3);
        }
    } else {
        if (v >= NP) return;
        float* __restrict__ dst = (which == 1) ? g_k : g_v;
        const int wp = v % WP;
        const int t  = v / WP;
        const int hp = t % HP;
        const int dp = t / HP;
        const int d = dp - 1, h = hp - 1, w = wp - 1;
        const bool inside = ((unsigned)d < DD) & ((unsigned)h < HH) & ((unsigned)w < WW);
        if (!inside) {
            #pragma unroll
            for (int o = 0; o < COUT; o++) dst[o * NP + v] = 0.f;
            return;
        }
        const int iv = (d * HH + h) * WW + w;
        float xs[CIN];
        #pragma unroll
        for (int c = 0; c < CIN; c++) xs[c] = x[c * NV + iv];
        #pragma unroll
        for (int o = 0; o < COUT; o++) {
            float a0 = 0.f, a1 = 0.f, a2 = 0.f, a3 = 0.f;
            #pragma unroll
            for (int c = 0; c < CIN; c += 4) {
                a0 = fmaf(sw[o * CIN + c + 0], xs[c + 0], a0);
                a1 = fmaf(sw[o * CIN + c + 1], xs[c + 1], a1);
                a2 = fmaf(sw[o * CIN + c + 2], xs[c + 2], a2);
                a3 = fmaf(sw[o * CIN + c + 3], xs[c + 3], a3);
            }
            dst[o * NP + v] = (a0 + a1) + (a2 + a3);
        }
    }
}

// ---------------------------------------------------------------------------
// Pass 2: per-channel scalar attention over the 27-voxel window.
// grid = (D/TD, H/TH, COUT); block = (WW, TH, TD) = 1024 threads.
// k/v halo tiles staged in smem; softmax WITHOUT max-subtraction (logits are
// bounded well below exp overflow; softmax is shift-invariant).
// ---------------------------------------------------------------------------
__global__ __launch_bounds__(WW * TH * TD)
void attn_kernel(const float* __restrict__ rel_h,
                 const float* __restrict__ rel_w,
                 const float* __restrict__ rel_d,
                 float* __restrict__ out) {
    __shared__ float sk[TILE_ELEMS];
    __shared__ float sv[TILE_ELEMS];
    __shared__ float sb[27];

    const int o  = blockIdx.z;
    const int d0 = blockIdx.x * TD;
    const int h0 = blockIdx.y * TH;
    const int tid = threadIdx.x + threadIdx.y * WW + threadIdx.z * (WW * TH);
    const int nthr = WW * TH * TD;

    // cooperative halo-tile load (rows of WP=66 floats are gmem-contiguous)
    const long base = (long)o * NP + (long)(d0 * HP + h0) * WP;
    const int rowblk = (TH + 2) * WP;   // 660
    for (int i = tid; i < TILE_ELEMS; i += nthr) {
        const int dl = i / rowblk;
        const int r  = i - dl * rowblk;
        const long g = base + (long)dl * (HP * WP) + r;
        sk[i] = g_k[g];
        sv[i] = g_v[g];
    }
    // per-channel 27-entry relative-position bias
    if (tid < 27) {
        const int kd = tid / 9, kh = (tid / 3) % 3, kw = tid % 3;
        const int grp = o >> 4, ci = o & 15;
        float b;
        if (grp == 0)      b = rel_d[ci * 3 + kw];
        else if (grp == 1) b = rel_h[ci * 3 + kd];
        else               b = rel_w[ci * 3 + kh];
        sb[tid] = b;
    }
    __syncthreads();

    const int w  = threadIdx.x;
    const int hl = threadIdx.y;
    const int dl = threadIdx.z;
    const int vox = ((d0 + dl) * HH + (h0 + hl)) * WW + w;

    const float q = g_q[o * NV + vox];

    float num = 0.f, den = 0.f;
    #pragma unroll
    for (int kd = 0; kd < 3; kd++) {
        #pragma unroll
        for (int kh = 0; kh < 3; kh++) {
            #pragma unroll
            for (int kw = 0; kw < 3; kw++) {
                const int j = (kd * 3 + kh) * 3 + kw;
                const int s = ((dl + kd) * (TH + 2) + (hl + kh)) * WP + (w + kw);
                const float kval = sk[s] + sb[j];
                const float ex   = __expf(q * kval);
                den += ex;
                num = fmaf(ex, sv[s], num);
            }
        }
    }
    out[o * NV + vox] = __fdividef(num, den);
}

extern "C" void kernel_launch(void* const* d_in, const int* in_sizes, int n_in,
                              void* d_out, int out_size) {
    const float* x     = (const float*)d_in[0];
    const float* Wq    = (const float*)d_in[1];
    const float* Wk    = (const float*)d_in[2];
    const float* Wv    = (const float*)d_in[3];
    const float* rel_h = (const float*)d_in[4];
    const float* rel_w = (const float*)d_in[5];
    const float* rel_d = (const float*)d_in[6];
    float* out = (float*)d_out;

    dim3 g1((NP + 255) / 256, 3);
    qkv_kernel<<<g1, 256>>>(x, Wq, Wk, Wv);

    dim3 g2(DD / TD, HH / TH, COUT);
    dim3 b2(WW, TH, TD);
    attn_kernel<<<g2, b2>>>(rel_h, rel_w, rel_d, out);
}

// round 2
// speedup vs baseline: 1.2509x; 1.2509x over previous
#include <cuda_runtime.h>

#define DD 24
#define HH 48
#define WW 64
#define NV (DD*HH*WW)        /* 73728  interior voxels */
#define DP (DD+2)
#define HP (HH+2)
#define WP (WW+2)
#define NP (DP*HP*WP)        /* 85800  padded voxels */
#define CIN 32
#define COUT 48

#define TD 2
#define TH 8
#define SROW 68                       /* padded smem row stride (floats): 68*4=272B, 16B-aligned rows */
#define NROWS ((TD+2)*(TH+2))         /* 40 */
#define TILE_LD (NROWS*WP)            /* 40*66 = 2640 elements actually loaded */

// scratch (allocation-free rule: __device__ globals)
__device__ float g_q[COUT * NV];
__device__ float g_k[COUT * NP];
__device__ float g_v[COUT * NP];

// ---------------------------------------------------------------------------
// Pass 1: 1x1x1 conv channel-GEMMs. blockIdx.y selects q(0)/k(1)/v(2).
// ---------------------------------------------------------------------------
__global__ void qkv_kernel(const float* __restrict__ x,
                           const float* __restrict__ Wq,
                           const float* __restrict__ Wk,
                           const float* __restrict__ Wv) {
    __shared__ float sw[COUT * CIN];
    const int which = blockIdx.y;
    const float* Wsel = (which == 0) ? Wq : ((which == 1) ? Wk : Wv);
    for (int i = threadIdx.x; i < COUT * CIN; i += blockDim.x) sw[i] = Wsel[i];
    __syncthreads();

    const int v = blockIdx.x * blockDim.x + threadIdx.x;

    if (which == 0) {
        if (v >= NV) return;
        float xs[CIN];
        #pragma unroll
        for (int c = 0; c < CIN; c++) xs[c] = x[c * NV + v];
        #pragma unroll
        for (int o = 0; o < COUT; o++) {
            float a0 = 0.f, a1 = 0.f, a2 = 0.f, a3 = 0.f;
            #pragma unroll
            for (int c = 0; c < CIN; c += 4) {
                a0 = fmaf(sw[o * CIN + c + 0], xs[c + 0], a0);
                a1 = fmaf(sw[o * CIN + c + 1], xs[c + 1], a1);
                a2 = fmaf(sw[o * CIN + c + 2], xs[c + 2], a2);
                a3 = fmaf(sw[o * CIN + c + 3], xs[c + 3], a3);
            }
            g_q[o * NV + v] = (a0 + a1) + (a2 + a3);
        }
    } else {
        if (v >= NP) return;
        float* __restrict__ dst = (which == 1) ? g_k : g_v;
        const int wp = v % WP;
        const int t  = v / WP;
        const int hp = t % HP;
        const int dp = t / HP;
        const int d = dp - 1, h = hp - 1, w = wp - 1;
        const bool inside = ((unsigned)d < DD) & ((unsigned)h < HH) & ((unsigned)w < WW);
        if (!inside) {
            #pragma unroll
            for (int o = 0; o < COUT; o++) dst[o * NP + v] = 0.f;
            return;
        }
        const int iv = (d * HH + h) * WW + w;
        float xs[CIN];
        #pragma unroll
        for (int c = 0; c < CIN; c++) xs[c] = x[c * NV + iv];
        #pragma unroll
        for (int o = 0; o < COUT; o++) {
            float a0 = 0.f, a1 = 0.f, a2 = 0.f, a3 = 0.f;
            #pragma unroll
            for (int c = 0; c < CIN; c += 4) {
                a0 = fmaf(sw[o * CIN + c + 0], xs[c + 0], a0);
                a1 = fmaf(sw[o * CIN + c + 1], xs[c + 1], a1);
                a2 = fmaf(sw[o * CIN + c + 2], xs[c + 2], a2);
                a3 = fmaf(sw[o * CIN + c + 3], xs[c + 3], a3);
            }
            dst[o * NP + v] = (a0 + a1) + (a2 + a3);
        }
    }
}

// ---------------------------------------------------------------------------
// Pass 2: per-channel attention, 4 outputs per thread along w.
// ---------------------------------------------------------------------------
__device__ __forceinline__ float ex2f(float x) {
    float y;
    asm("ex2.approx.ftz.f32 %0, %1;" : "=f"(y) : "f"(x));
    return y;
}

// GRP: 0 -> bias index kw, 1 -> kd, 2 -> kh  (compile-time)
template<int GRP>
__device__ __forceinline__ void attn_core(const float* __restrict__ sk,
                                          const float* __restrict__ sv,
                                          const float qs[4],
                                          const float qb[3][4],
                                          int dl, int hl, int w0,
                                          float num[4], float den[4]) {
    #pragma unroll
    for (int kd = 0; kd < 3; kd++) {
        #pragma unroll
        for (int kh = 0; kh < 3; kh++) {
            const int rb = ((dl + kd) * (TH + 2) + (hl + kh)) * SROW + w0;
            const float4 ka = *(const float4*)(sk + rb);
            const float2 kc = *(const float2*)(sk + rb + 4);
            const float4 va = *(const float4*)(sv + rb);
            const float2 vc = *(const float2*)(sv + rb + 4);
            const float kk[6] = {ka.x, ka.y, ka.z, ka.w, kc.x, kc.y};
            const float vv[6] = {va.x, va.y, va.z, va.w, vc.x, vc.y};
            #pragma unroll
            for (int kw = 0; kw < 3; kw++) {
                const int sel = (GRP == 0) ? kw : ((GRP == 1) ? kd : kh);
                #pragma unroll
                for (int wi = 0; wi < 4; wi++) {
                    const float arg = fmaf(qs[wi], kk[wi + kw], qb[sel][wi]);
                    const float ex  = ex2f(arg);
                    den[wi] += ex;
                    num[wi] = fmaf(ex, vv[wi + kw], num[wi]);
                }
            }
        }
    }
}

__global__ __launch_bounds__(256)
void attn_kernel(const float* __restrict__ rel_h,
                 const float* __restrict__ rel_w,
                 const float* __restrict__ rel_d,
                 float* __restrict__ out) {
    __shared__ float sk[NROWS * SROW];
    __shared__ float sv[NROWS * SROW];

    const int o  = blockIdx.z;
    const int d0 = blockIdx.x * TD;
    const int h0 = blockIdx.y * TH;
    const int tid = threadIdx.x + (threadIdx.y << 4) + (threadIdx.z << 7);

    // cooperative halo-tile load into padded-stride smem
    const long base = (long)o * NP + (long)(d0 * HP + h0) * WP;
    for (int i = tid; i < TILE_LD; i += 256) {
        const int row = i / WP;
        const int col = i - row * WP;
        const int dl  = row / (TH + 2);
        const int hh  = row - dl * (TH + 2);
        const long g  = base + (long)dl * (HP * WP) + (long)hh * WP + col;
        const int s   = row * SROW + col;
        sk[s] = g_k[g];
        sv[s] = g_v[g];
    }
    __syncthreads();

    const int w0 = threadIdx.x << 2;       // 0..60, 4 outputs per thread
    const int hl = threadIdx.y;
    const int dl = threadIdx.z;
    const int vox0 = ((d0 + dl) * HH + (h0 + hl)) * WW + w0;

    // q (16B-aligned), prescaled by log2(e)
    const float4 q4 = *(const float4*)(g_q + (long)o * NV + vox0);
    const float L2E = 1.4426950408889634f;
    float qs[4] = {q4.x * L2E, q4.y * L2E, q4.z * L2E, q4.w * L2E};

    // 3 distinct bias values for this channel
    const int grp = o >> 4, ci = o & 15;
    const float* rel = (grp == 0) ? (rel_d + ci * 3)
                     : (grp == 1) ? (rel_h + ci * 3)
                                  : (rel_w + ci * 3);
    const float b0 = rel[0], b1 = rel[1], b2 = rel[2];
    float qb[3][4];
    #pragma unroll
    for (int wi = 0; wi < 4; wi++) {
        qb[0][wi] = qs[wi] * b0;
        qb[1][wi] = qs[wi] * b1;
        qb[2][wi] = qs[wi] * b2;
    }

    float num[4] = {0.f, 0.f, 0.f, 0.f};
    float den[4] = {0.f, 0.f, 0.f, 0.f};

    if (grp == 0)      attn_core<0>(sk, sv, qs, qb, dl, hl, w0, num, den);
    else if (grp == 1) attn_core<1>(sk, sv, qs, qb, dl, hl, w0, num, den);
    else               attn_core<2>(sk, sv, qs, qb, dl, hl, w0, num, den);

    float4 r;
    r.x = __fdividef(num[0], den[0]);
    r.y = __fdividef(num[1], den[1]);
    r.z = __fdividef(num[2], den[2]);
    r.w = __fdividef(num[3], den[3]);
    *(float4*)(out + (long)o * NV + vox0) = r;
}

extern "C" void kernel_launch(void* const* d_in, const int* in_sizes, int n_in,
                              void* d_out, int out_size) {
    const float* x     = (const float*)d_in[0];
    const float* Wq    = (const float*)d_in[1];
    const float* Wk    = (const float*)d_in[2];
    const float* Wv    = (const float*)d_in[3];
    const float* rel_h = (const float*)d_in[4];
    const float* rel_w = (const float*)d_in[5];
    const float* rel_d = (const float*)d_in[6];
    float* out = (float*)d_out;

    dim3 g1((NP + 255) / 256, 3);
    qkv_kernel<<<g1, 256>>>(x, Wq, Wk, Wv);

    dim3 g2(DD / TD, HH / TH, COUT);
    dim3 b2(16, TH, TD);
    attn_kernel<<<g2, b2>>>(rel_h, rel_w, rel_d, out);
}